// round 4
// baseline (speedup 1.0000x reference)
#include <cuda_runtime.h>
#include <cuda_bf16.h>

// Depthwise conv 31x31, pad 15, stride 1, fp32.
// x: [32, 384, 56, 56], w: [384, 1, 31, 31], bias: [384], out: [32, 384, 56, 56]
//
// One block per (n,c) plane. Single smem copy of the padded plane; even pairs
// loaded with conflict-free LDS.64 (SSTRIDE=88 -> 16 distinct bank-pairs per
// 16-lane phase); odd pairs built in registers from adjacent even pairs
// (2 MOVs on the alu pipe). Weights held in small register rings. Inner loop
// is pure fma.rn.f32x2.

#define ROWS 86           // 56 + 2*15
#define COLS 86
#define SSTRIDE 88        // (88/2)=44 = 12 mod 16 -> conflict-free pair banks
#define NTHREADS 224      // 56 rows * 4 col-groups of 14 outputs

typedef unsigned long long u64;

#define FMA2(a, x, w) asm("fma.rn.f32x2 %0, %1, %2, %0;" : "+l"(a) : "l"(x), "l"(w))

__global__ void __launch_bounds__(NTHREADS, 4)
dwconv31_f32x2_v2_kernel(const float* __restrict__ x,
                         const float* __restrict__ w,
                         const float* __restrict__ bias,
                         float* __restrict__ out)
{
    const int plane = blockIdx.x;          // n*384 + c
    const int ch = plane - (plane / 384) * 384;

    extern __shared__ float sm[];
    float* inA = sm;                                   // ROWS * SSTRIDE floats
    u64* wd = (u64*)(sm + ROWS * SSTRIDE);             // 961 duplicated weight pairs

    const float* xp = x + (long long)plane * (56 * 56);

    // Stage duplicated weights: wd[t] = (w_t, w_t)
    for (int i = threadIdx.x; i < 961; i += NTHREADS) {
        float v = w[ch * 961 + i];
        u64 p;
        asm("mov.b64 %0, {%1, %1};" : "=l"(p) : "f"(v));
        wd[i] = p;
    }

    // Stage padded input plane (zero halo).
    for (int i = threadIdx.x; i < ROWS * COLS; i += NTHREADS) {
        int r = i / COLS;
        int c = i - r * COLS;
        int gy = r - 15, gx = c - 15;
        float v = 0.0f;
        if ((unsigned)gy < 56u && (unsigned)gx < 56u)
            v = xp[gy * 56 + gx];
        inA[r * SSTRIDE + c] = v;
    }
    __syncthreads();

    const int y  = threadIdx.x >> 2;          // 0..55 output row
    const int xx = (threadIdx.x & 3) * 14;    // 0,14,28,42 output col base

    u64 acc[7];
#pragma unroll
    for (int j = 0; j < 7; ++j) acc[j] = 0ull;

#pragma unroll 1
    for (int dy = 0; dy < 31; ++dy) {
        const u64* pE = (const u64*)(inA + (y + dy) * SSTRIDE + xx);
        const u64* wr = wd + dy * 31;   // taps 0..30 (duplicated pairs)

        u64 wE[8];   // even-tap weight ring: wE[e&7] = dup(w[2e])
        u64 wO[8];   // odd-tap weight ring:  wO[o&7] = dup(w[2o+1])
        u64 vPrev, vCur, vO;

        // step 0
        vCur = pE[0];
        wE[0] = wr[0];
        FMA2(acc[0], vCur, wE[0]);

#pragma unroll
        for (int i = 1; i <= 21; ++i) {
            vPrev = vCur;
            vCur = pE[i];
            if (i <= 15) {
                wE[i & 7] = wr[2 * i];
                wO[(i - 1) & 7] = wr[2 * i - 1];
            }
            // vO = (hi(vPrev), lo(vCur)) = odd pair (x_{2i-1}, x_{2i})
            asm("{ .reg .b32 pl, ph, cl, chh;\n"
                "  mov.b64 {pl, ph}, %1;\n"
                "  mov.b64 {cl, chh}, %2;\n"
                "  mov.b64 %0, {ph, cl}; }\n"
                : "=l"(vO) : "l"(vPrev), "l"(vCur));

            // even taps with e + j == i
            {
                const int elo = (i - 6 > 0) ? (i - 6) : 0;
                const int ehi = (i < 15) ? i : 15;
#pragma unroll
                for (int e = elo; e <= ehi; ++e)
                    FMA2(acc[i - e], vCur, wE[e & 7]);
            }
            // odd taps with o + j == i - 1
            {
                const int olo = (i - 7 > 0) ? (i - 7) : 0;
                const int ohi = (i - 1 < 14) ? (i - 1) : 14;
#pragma unroll
                for (int o = olo; o <= ohi; ++o)
                    FMA2(acc[i - 1 - o], vO, wO[o & 7]);
            }
        }
    }

    const float b = bias[ch];
    float* op = out + (long long)plane * (56 * 56) + y * 56 + xx;
#pragma unroll
    for (int j = 0; j < 7; ++j) {
        float lo, hi;
        asm("mov.b64 {%0, %1}, %2;" : "=f"(lo), "=f"(hi) : "l"(acc[j]));
        float2 v = make_float2(lo + b, hi + b);
        *reinterpret_cast<float2*>(op + 2 * j) = v;
    }
}

extern "C" void kernel_launch(void* const* d_in, const int* in_sizes, int n_in,
                              void* d_out, int out_size)
{
    const float* x    = (const float*)d_in[0];
    const float* w    = (const float*)d_in[1];
    const float* bias = (const float*)d_in[2];
    float* out = (float*)d_out;

    const int smem_bytes = (ROWS * SSTRIDE) * 4 + 961 * 8;  // 37,960 B

    cudaFuncSetAttribute(dwconv31_f32x2_v2_kernel,
                         cudaFuncAttributeMaxDynamicSharedMemorySize, smem_bytes);

    dim3 grid(32 * 384);
    dim3 block(NTHREADS);
    dwconv31_f32x2_v2_kernel<<<grid, block, smem_bytes>>>(x, w, bias, out);
}

// round 5
// speedup vs baseline: 1.1571x; 1.1571x over previous
#include <cuda_runtime.h>
#include <cuda_bf16.h>

// Depthwise conv 31x31, pad 15, stride 1, fp32.
// x: [32, 384, 56, 56], w: [384, 1, 31, 31], bias: [384], out: [32, 384, 56, 56]
//
// One block per (n,c) plane. Padded plane staged in smem twice (plain + one-
// float-shifted copy) so every even/odd tap pair is an aligned LDS.64.
// SSTRIDE=88: pair-bank = 12*y + 7*g (mod 16); 12*dy in {4,8,12} never equals
// 7*dg in {2,5,7,9,11,14} -> conflict-free across the 4 rows x 4 col-groups of
// each 16-lane phase. Weights duplicated to (w,w) u64, rows padded to 32 so
// each dy needs only 16 ld.shared.v2.u64 broadcasts. Inner loop is pure
// fma.rn.f32x2 (2x fp32 throughput).

#define ROWS 86           // 56 + 2*15
#define COLS 86
#define SSTRIDE 88        // 44 mod 16 = 12 -> conflict-free (see header)
#define WSTRIDE 32        // weight taps padded 31 -> 32 for 16B alignment
#define NTHREADS 224      // 56 rows * 4 col-groups of 14 outputs

typedef unsigned long long u64;

#define FMA2(a, x, w) asm("fma.rn.f32x2 %0, %1, %2, %0;" : "+l"(a) : "l"(x), "l"(w))

__global__ void __launch_bounds__(NTHREADS, 3)
dwconv31_f32x2_v3_kernel(const float* __restrict__ x,
                         const float* __restrict__ w,
                         const float* __restrict__ bias,
                         float* __restrict__ out)
{
    const int plane = blockIdx.x;          // n*384 + c
    const int ch = plane - (plane / 384) * 384;

    extern __shared__ float sm[];
    // Layout: [wd: 31*32 u64][inA: ROWS*SSTRIDE f32][inB: ROWS*SSTRIDE f32]
    u64* wd = (u64*)sm;                                  // 16B aligned
    float* inA = sm + (31 * WSTRIDE * 2);                // u64 = 2 floats
    float* inB = inA + ROWS * SSTRIDE;

    const float* xp = x + (long long)plane * (56 * 56);

    // Stage duplicated weights, rows padded to WSTRIDE: wd[dy*32 + t] = (w,w)
    for (int i = threadIdx.x; i < 31 * WSTRIDE; i += NTHREADS) {
        int dy = i >> 5, t = i & 31;
        float v = (t < 31) ? w[ch * 961 + dy * 31 + t] : 0.0f;
        u64 p;
        asm("mov.b64 %0, {%1, %1};" : "=l"(p) : "f"(v));
        wd[i] = p;
    }

    // Stage padded input plane (zero halo) + one-float-shifted copy.
    for (int i = threadIdx.x; i < ROWS * COLS; i += NTHREADS) {
        int r = i / COLS;
        int c = i - r * COLS;
        int gy = r - 15, gx = c - 15;
        float v = 0.0f;
        if ((unsigned)gy < 56u && (unsigned)gx < 56u)
            v = xp[gy * 56 + gx];
        inA[r * SSTRIDE + c] = v;
        if (c > 0)         inB[r * SSTRIDE + c - 1] = v;
        if (c == COLS - 1) inB[r * SSTRIDE + c] = 0.0f;
    }
    __syncthreads();

    const int y  = threadIdx.x >> 2;          // 0..55 output row
    const int xx = (threadIdx.x & 3) * 14;    // 0,14,28,42 output col base

    u64 acc[7];
#pragma unroll
    for (int j = 0; j < 7; ++j) acc[j] = 0ull;

#pragma unroll 1
    for (int dy = 0; dy < 31; ++dy) {
        const u64* pA = (const u64*)(inA + (y + dy) * SSTRIDE + xx);
        const u64* pB = (const u64*)(inB + (y + dy) * SSTRIDE + xx);
        const ulonglong2* wr2 = (const ulonglong2*)(wd + dy * WSTRIDE);

        // wr2[m].x = dup(w[2m]) (even tap e=m), wr2[m].y = dup(w[2m+1]) (odd tap o=m)
#pragma unroll
        for (int m = 0; m < 16; ++m) {
            ulonglong2 wp = wr2[m];
#pragma unroll
            for (int j = 0; j < 7; ++j)
                FMA2(acc[j], pA[m + j], wp.x);      // even taps, CSE'd loads
            if (m < 15) {
#pragma unroll
                for (int j = 0; j < 7; ++j)
                    FMA2(acc[j], pB[m + j], wp.y);  // odd taps
            }
        }
    }

    const float b = bias[ch];
    float* op = out + (long long)plane * (56 * 56) + y * 56 + xx;
#pragma unroll
    for (int j = 0; j < 7; ++j) {
        float lo, hi;
        asm("mov.b64 {%0, %1}, %2;" : "=f"(lo), "=f"(hi) : "l"(acc[j]));
        float2 v = make_float2(lo + b, hi + b);
        *reinterpret_cast<float2*>(op + 2 * j) = v;
    }
}

extern "C" void kernel_launch(void* const* d_in, const int* in_sizes, int n_in,
                              void* d_out, int out_size)
{
    const float* x    = (const float*)d_in[0];
    const float* w    = (const float*)d_in[1];
    const float* bias = (const float*)d_in[2];
    float* out = (float*)d_out;

    // wd: 31*32*8 = 7936 B; inA+inB: 2*86*88*4 = 60544 B; total 68480 B
    const int smem_bytes = 31 * WSTRIDE * 8 + 2 * ROWS * SSTRIDE * 4;

    cudaFuncSetAttribute(dwconv31_f32x2_v3_kernel,
                         cudaFuncAttributeMaxDynamicSharedMemorySize, smem_bytes);

    dim3 grid(32 * 384);
    dim3 block(NTHREADS);
    dwconv31_f32x2_v3_kernel<<<grid, block, smem_bytes>>>(x, w, bias, out);
}

// round 6
// speedup vs baseline: 1.1573x; 1.0002x over previous
#include <cuda_runtime.h>
#include <cuda_bf16.h>

// Depthwise conv 31x31, pad 15, stride 1, fp32.
// x: [32, 384, 56, 56], w: [384, 1, 31, 31], bias: [384], out: [32, 384, 56, 56]
//
// One block per (n,c) plane. Padded plane staged in smem twice (plain + one-
// float-shifted copy) so every even/odd tap pair is an aligned LDS.64.
// SSTRIDE=88: pair-bank delta = 12*dy + 7*dg (mod 16); 12*dy in {4,8,12}
// never meets -7*dg in {9,2,11,7,14,5} -> conflict-free across each 16-lane
// phase (4 rows x 4 col-groups). Weights duplicated to (w,w) u64, rows padded
// to 32 taps so each dy needs only 8 LDS.128 broadcasts. Inner loop is pure
// fma.rn.f32x2.
//
// R5 change: force PreferredSharedMemoryCarveout = 100% so 3 CTAs / SM are
// actually resident (default carveout capped us at 2 -> warp starvation,
// issue=42.5%, fma=58.9%).

#define ROWS 86           // 56 + 2*15
#define COLS 86
#define SSTRIDE 88        // 44 mod 16 = 12 -> conflict-free (see header)
#define WSTRIDE 32        // weight taps padded 31 -> 32 for 16B alignment
#define NTHREADS 224      // 56 rows * 4 col-groups of 14 outputs

typedef unsigned long long u64;

#define FMA2(a, x, w) asm("fma.rn.f32x2 %0, %1, %2, %0;" : "+l"(a) : "l"(x), "l"(w))

__global__ void __launch_bounds__(NTHREADS, 3)
dwconv31_f32x2_v4_kernel(const float* __restrict__ x,
                         const float* __restrict__ w,
                         const float* __restrict__ bias,
                         float* __restrict__ out)
{
    const int plane = blockIdx.x;          // n*384 + c
    const int ch = plane - (plane / 384) * 384;

    extern __shared__ float sm[];
    // Layout: [wd: 31*32 u64][inA: ROWS*SSTRIDE f32][inB: ROWS*SSTRIDE f32]
    u64* wd = (u64*)sm;                                  // 16B aligned
    float* inA = sm + (31 * WSTRIDE * 2);                // u64 = 2 floats
    float* inB = inA + ROWS * SSTRIDE;

    const float* xp = x + (long long)plane * (56 * 56);

    // Stage duplicated weights, rows padded to WSTRIDE: wd[dy*32 + t] = (w,w)
    for (int i = threadIdx.x; i < 31 * WSTRIDE; i += NTHREADS) {
        int dy = i >> 5, t = i & 31;
        float v = (t < 31) ? w[ch * 961 + dy * 31 + t] : 0.0f;
        u64 p;
        asm("mov.b64 %0, {%1, %1};" : "=l"(p) : "f"(v));
        wd[i] = p;
    }

    // Stage padded input plane (zero halo) + one-float-shifted copy.
    for (int i = threadIdx.x; i < ROWS * COLS; i += NTHREADS) {
        int r = i / COLS;
        int c = i - r * COLS;
        int gy = r - 15, gx = c - 15;
        float v = 0.0f;
        if ((unsigned)gy < 56u && (unsigned)gx < 56u)
            v = xp[gy * 56 + gx];
        inA[r * SSTRIDE + c] = v;
        if (c > 0)         inB[r * SSTRIDE + c - 1] = v;
        if (c == COLS - 1) inB[r * SSTRIDE + c] = 0.0f;
    }
    __syncthreads();

    const int y  = threadIdx.x >> 2;          // 0..55 output row
    const int xx = (threadIdx.x & 3) * 14;    // 0,14,28,42 output col base

    u64 acc[7];
#pragma unroll
    for (int j = 0; j < 7; ++j) acc[j] = 0ull;

#pragma unroll 1
    for (int dy = 0; dy < 31; ++dy) {
        const u64* pA = (const u64*)(inA + (y + dy) * SSTRIDE + xx);
        const u64* pB = (const u64*)(inB + (y + dy) * SSTRIDE + xx);
        const ulonglong2* wr2 = (const ulonglong2*)(wd + dy * WSTRIDE);

        // wr2[m].x = dup(w[2m]) (even tap e=m), wr2[m].y = dup(w[2m+1]) (odd tap o=m)
#pragma unroll
        for (int m = 0; m < 16; ++m) {
            ulonglong2 wp = wr2[m];
#pragma unroll
            for (int j = 0; j < 7; ++j)
                FMA2(acc[j], pA[m + j], wp.x);      // even taps (loads CSE'd)
            if (m < 15) {
#pragma unroll
                for (int j = 0; j < 7; ++j)
                    FMA2(acc[j], pB[m + j], wp.y);  // odd taps
            }
        }
    }

    const float b = bias[ch];
    float* op = out + (long long)plane * (56 * 56) + y * 56 + xx;
#pragma unroll
    for (int j = 0; j < 7; ++j) {
        float lo, hi;
        asm("mov.b64 {%0, %1}, %2;" : "=f"(lo), "=f"(hi) : "l"(acc[j]));
        float2 v = make_float2(lo + b, hi + b);
        *reinterpret_cast<float2*>(op + 2 * j) = v;
    }
}

extern "C" void kernel_launch(void* const* d_in, const int* in_sizes, int n_in,
                              void* d_out, int out_size)
{
    const float* x    = (const float*)d_in[0];
    const float* w    = (const float*)d_in[1];
    const float* bias = (const float*)d_in[2];
    float* out = (float*)d_out;

    // wd: 31*32*8 = 7936 B; inA+inB: 2*86*88*4 = 60544 B; total 68480 B
    const int smem_bytes = 31 * WSTRIDE * 8 + 2 * ROWS * SSTRIDE * 4;

    static int configured = -1;
    if (configured < 0) {
        cudaFuncSetAttribute(dwconv31_f32x2_v4_kernel,
                             cudaFuncAttributeMaxDynamicSharedMemorySize, smem_bytes);
        // Force max shared-memory carveout so 3 CTAs (205 KB) fit per SM.
        cudaFuncSetAttribute(dwconv31_f32x2_v4_kernel,
                             cudaFuncAttributePreferredSharedMemoryCarveout, 100);
        configured = 1;
    }

    dim3 grid(32 * 384);
    dim3 block(NTHREADS);
    dwconv31_f32x2_v4_kernel<<<grid, block, smem_bytes>>>(x, w, bias, out);
}

// round 7
// speedup vs baseline: 1.1827x; 1.0219x over previous
#include <cuda_runtime.h>
#include <cuda_bf16.h>

// Depthwise conv 31x31, pad 15, stride 1, fp32.
// x: [32, 384, 56, 56], w: [384, 1, 31, 31], bias: [384], out: [32, 384, 56, 56]
//
// One block per (n,c) plane, 112 threads = 28 row-pairs x 4 col-groups.
// Each thread computes 2 output rows x 14 cols (14 packed f32x2 accumulators),
// so every input LDS.64 feeds FMAs for BOTH rows -> smem crossbar traffic per
// FMA is halved vs v4 (which was crossbar/fma co-bound at ~60%).
//
// Padded plane staged twice (plain + one-float-shifted) so even/odd tap pairs
// are aligned LDS.64. SSTRIDE=92: pair-bank delta = 12*dy2 + 7*dg (mod 16),
// 12*dy2 in {12,8,4} never cancels 7*dg in {9,2,11,7,14,5} -> conflict-free.
// Weights duplicated (w,w) u64, rows padded to 32, with zero rows at logical
// indices -1 and 31 (WZ rows 0 and 32) so the 32-iteration input-row loop is
// branch-free. Inner loop is pure fma.rn.f32x2.

#define ROWS 86           // 56 + 2*15
#define COLS 86
#define SSTRIDE 92        // 92 mod 16 = 12 -> conflict-free for y2-mapping
#define WSTRIDE 32        // weight taps padded 31 -> 32 (u64 units per row)
#define NTHREADS 112      // 28 row-pairs * 4 col-groups

typedef unsigned long long u64;

#define FMA2(a, x, w) asm("fma.rn.f32x2 %0, %1, %2, %0;" : "+l"(a) : "l"(x), "l"(w))

__global__ void __launch_bounds__(NTHREADS, 3)
dwconv31_f32x2_v5_kernel(const float* __restrict__ x,
                         const float* __restrict__ w,
                         const float* __restrict__ bias,
                         float* __restrict__ out)
{
    const int plane = blockIdx.x;          // n*384 + c
    const int ch = plane - (plane / 384) * 384;

    extern __shared__ float sm[];
    // Layout: [inA: ROWS*SSTRIDE f32][inB: ROWS*SSTRIDE f32][WZ: 33*32 u64]
    float* inA = sm;
    float* inB = sm + ROWS * SSTRIDE;
    u64* WZ = (u64*)(sm + 2 * ROWS * SSTRIDE);   // 63296 B offset, 16B aligned

    const float* xp = x + (long long)plane * (56 * 56);

    // Stage duplicated weights with zero guard rows:
    // WZ[k][t] = dup(w[(k-1)*31 + t]) for k=1..31 (t<31), else 0.
    for (int i = threadIdx.x; i < 33 * WSTRIDE; i += NTHREADS) {
        int k = i >> 5, t = i & 31;
        float v = 0.0f;
        if (k >= 1 && k <= 31 && t < 31)
            v = w[ch * 961 + (k - 1) * 31 + t];
        u64 p;
        asm("mov.b64 %0, {%1, %1};" : "=l"(p) : "f"(v));
        WZ[i] = p;
    }

    // Stage padded input plane (zero halo) + one-float-shifted copy.
    for (int i = threadIdx.x; i < ROWS * COLS; i += NTHREADS) {
        int r = i / COLS;
        int c = i - r * COLS;
        int gy = r - 15, gx = c - 15;
        float v = 0.0f;
        if ((unsigned)gy < 56u && (unsigned)gx < 56u)
            v = xp[gy * 56 + gx];
        inA[r * SSTRIDE + c] = v;
        if (c > 0)         inB[r * SSTRIDE + c - 1] = v;
        if (c == COLS - 1) inB[r * SSTRIDE + c] = 0.0f;
    }
    __syncthreads();

    const int y2 = threadIdx.x >> 2;          // 0..27
    const int y  = y2 * 2;                    // output row base (even)
    const int xx = (threadIdx.x & 3) * 14;    // 0,14,28,42 output col base

    u64 acc0[7], acc1[7];
#pragma unroll
    for (int j = 0; j < 7; ++j) { acc0[j] = 0ull; acc1[j] = 0ull; }

#pragma unroll 1
    for (int r = 0; r < 32; ++r) {
        // Input row y + r feeds: out row y with weight row r   (WZ row r+1)
        //                        out row y+1 with weight row r-1 (WZ row r)
        const u64* pA = (const u64*)(inA + (y + r) * SSTRIDE + xx);
        const u64* pB = (const u64*)(inB + (y + r) * SSTRIDE + xx);
        const ulonglong2* w0 = (const ulonglong2*)(WZ + (r + 1) * WSTRIDE);
        const ulonglong2* w1 = (const ulonglong2*)(WZ + r * WSTRIDE);

        // w*[m].x = dup(w[2m]) (even tap), w*[m].y = dup(w[2m+1]) (odd tap)
#pragma unroll
        for (int m = 0; m < 16; ++m) {
            ulonglong2 wp0 = w0[m];
            ulonglong2 wp1 = w1[m];
#pragma unroll
            for (int j = 0; j < 7; ++j) {
                u64 vA = pA[m + j];            // CSE'd across m
                FMA2(acc0[j], vA, wp0.x);
                FMA2(acc1[j], vA, wp1.x);
            }
            if (m < 15) {
#pragma unroll
                for (int j = 0; j < 7; ++j) {
                    u64 vB = pB[m + j];
                    FMA2(acc0[j], vB, wp0.y);
                    FMA2(acc1[j], vB, wp1.y);
                }
            }
        }
    }

    const float b = bias[ch];
    float* op0 = out + (long long)plane * (56 * 56) + y * 56 + xx;
    float* op1 = op0 + 56;
#pragma unroll
    for (int j = 0; j < 7; ++j) {
        float lo, hi;
        asm("mov.b64 {%0, %1}, %2;" : "=f"(lo), "=f"(hi) : "l"(acc0[j]));
        *reinterpret_cast<float2*>(op0 + 2 * j) = make_float2(lo + b, hi + b);
        asm("mov.b64 {%0, %1}, %2;" : "=f"(lo), "=f"(hi) : "l"(acc1[j]));
        *reinterpret_cast<float2*>(op1 + 2 * j) = make_float2(lo + b, hi + b);
    }
}

extern "C" void kernel_launch(void* const* d_in, const int* in_sizes, int n_in,
                              void* d_out, int out_size)
{
    const float* x    = (const float*)d_in[0];
    const float* w    = (const float*)d_in[1];
    const float* bias = (const float*)d_in[2];
    float* out = (float*)d_out;

    // inA+inB: 2*86*92*4 = 63296 B; WZ: 33*32*8 = 8448 B; total 71744 B
    const int smem_bytes = 2 * ROWS * SSTRIDE * 4 + 33 * WSTRIDE * 8;

    cudaFuncSetAttribute(dwconv31_f32x2_v5_kernel,
                         cudaFuncAttributeMaxDynamicSharedMemorySize, smem_bytes);
    cudaFuncSetAttribute(dwconv31_f32x2_v5_kernel,
                         cudaFuncAttributePreferredSharedMemoryCarveout, 100);

    dim3 grid(32 * 384);
    dim3 block(NTHREADS);
    dwconv31_f32x2_v5_kernel<<<grid, block, smem_bytes>>>(x, w, bias, out);
}

// round 8
// speedup vs baseline: 1.1972x; 1.0123x over previous
#include <cuda_runtime.h>
#include <cuda_bf16.h>

// Depthwise conv 31x31, pad 15, stride 1, fp32.
// x: [32, 384, 56, 56], w: [384, 1, 31, 31], bias: [384], out: [32, 384, 56, 56]
//
// v6: one block per (n,c) plane, 224 threads = 2 K-halves x (28 row-pairs x 4
// col-groups). Each logical thread computes 2 output rows x 14 cols as 14
// packed f32x2 accumulators over HALF the 31 tap-rows; halves combine via a
// smem reduction. Full 32-lane warps (no half-warp pipe tax) and 21 warps/SM.
//
// Single smem copy of the padded plane. For an output pair and aligned input
// pair pf=(a,b):  acc += pf*dup(w_t) + swap(pf)*(w_{t+1}, w_{t-1}),  t even,
// w_{-1}=w_{31}=0. swap(pf) is 2 MOVs (alu), CSE'd per input pair.
// SSTRIDE=92 (=12 mod 16): pair-bank delta = 12*dy2 + 7*dg (mod 16);
// {4,8,12} never meets {2,5,7,9,11,14} -> conflict-free LDS.64.
// Weight rows stored as 16 ulonglong2: [dup(w_2e), (w_{2e+1},w_{2e-1})],
// with zero guard rows so the r-loop is branch-free.

#define ROWS 86           // 56 + 2*15
#define COLS 86
#define SSTRIDE 92        // floats per row; 92 mod 16 = 12 -> conflict-free
#define PJ (SSTRIDE/2)    // 46 u64 pairs per row
#define WROW 32           // u64 entries per weight row (16 x ulonglong2)
#define NTHREADS 224

typedef unsigned long long u64;

#define FMA2(a, x, w) asm("fma.rn.f32x2 %0, %1, %2, %0;" : "+l"(a) : "l"(x), "l"(w))

__global__ void __launch_bounds__(NTHREADS, 3)
dwconv31_f32x2_v6_kernel(const float* __restrict__ x,
                         const float* __restrict__ w,
                         const float* __restrict__ bias,
                         float* __restrict__ out)
{
    const int plane = blockIdx.x;          // n*384 + c
    const int ch = plane - (plane / 384) * 384;

    extern __shared__ float sm[];
    // [inA: 86*92 f32 = 31648 B][WZ: 33*32 u64 = 8448 B][scratch: 1568 u64 = 12544 B]
    float* inA = sm;
    u64* WZ = (u64*)(sm + ROWS * SSTRIDE);
    u64* scratch = WZ + 33 * WROW;

    const float* xp = x + (long long)plane * (56 * 56);

    // Stage weights. WZ row k holds logical tap-row kk = k-1 (zeros if kk
    // outside 0..30). Entry layout per row: [2e] = dup(w_{2e});
    // [2e+1] = (lo=w_{2e+1} or 0, hi=w_{2e-1} or 0).
    for (int i = threadIdx.x; i < 33 * WROW; i += NTHREADS) {
        int k = i >> 5, s = i & 31, e = s >> 1;
        int kk = k - 1;
        float lo = 0.0f, hi = 0.0f;
        if (kk >= 0 && kk < 31) {
            const float* wr = w + ch * 961 + kk * 31;
            if ((s & 1) == 0) {
                lo = hi = wr[2 * e];
            } else {
                lo = (2 * e + 1 < 31) ? wr[2 * e + 1] : 0.0f;
                hi = (e > 0) ? wr[2 * e - 1] : 0.0f;
            }
        }
        u64 p;
        asm("mov.b64 %0, {%1, %2};" : "=l"(p) : "f"(lo), "f"(hi));
        WZ[i] = p;
    }

    // Stage padded input plane (zero halo).
    for (int i = threadIdx.x; i < ROWS * COLS; i += NTHREADS) {
        int r = i / COLS;
        int c = i - r * COLS;
        int gy = r - 15, gx = c - 15;
        float v = 0.0f;
        if ((unsigned)gy < 56u && (unsigned)gx < 56u)
            v = xp[gy * 56 + gx];
        inA[r * SSTRIDE + c] = v;
    }
    __syncthreads();

    const int half = (threadIdx.x >= 112);
    const int t    = threadIdx.x - half * 112;   // 0..111
    const int y2 = t >> 2;                       // 0..27
    const int y  = y2 * 2;                       // output row base
    const int g  = t & 3;                        // col group
    const int rbase = half * 16;

    u64 acc0[7], acc1[7];
#pragma unroll
    for (int j = 0; j < 7; ++j) { acc0[j] = 0ull; acc1[j] = 0ull; }

#pragma unroll 1
    for (int r = 0; r < 16; ++r) {
        const int rr = rbase + r;
        // Input row y+rr feeds: out row y   with logical weight row rr   (WZ rr+1)
        //                       out row y+1 with logical weight row rr-1 (WZ rr)
        const u64* prow = (const u64*)inA + (y + rr) * PJ + g * 7;
        const ulonglong2* W0 = (const ulonglong2*)(WZ + (rr + 1) * WROW);
        const ulonglong2* W1 = (const ulonglong2*)(WZ + rr * WROW);

#pragma unroll
        for (int e = 0; e < 16; ++e) {
            ulonglong2 wa = W0[e];   // .x = dup even tap, .y = cross pair
            ulonglong2 wb = W1[e];
#pragma unroll
            for (int j = 0; j < 7; ++j) {
                u64 pf = prow[e + j];                 // CSE'd across e+j
                u64 pr;                               // swapped pair (CSE'd)
                asm("{\n\t.reg .b32 lo, hi;\n\t"
                    "mov.b64 {lo, hi}, %1;\n\t"
                    "mov.b64 %0, {hi, lo};\n\t}"
                    : "=l"(pr) : "l"(pf));
                FMA2(acc0[j], pf, wa.x);
                FMA2(acc0[j], pr, wa.y);
                FMA2(acc1[j], pf, wb.x);
                FMA2(acc1[j], pr, wb.y);
            }
        }
    }

    // Split-K reduction: half1 publishes, half0 combines and writes out.
    if (half) {
#pragma unroll
        for (int j = 0; j < 7; ++j) {
            scratch[j * 112 + t]       = acc0[j];
            scratch[(7 + j) * 112 + t] = acc1[j];
        }
    }
    __syncthreads();
    if (!half) {
        const float b = bias[ch];
        float* op0 = out + (long long)plane * (56 * 56) + y * 56 + g * 14;
        float* op1 = op0 + 56;
#pragma unroll
        for (int j = 0; j < 7; ++j) {
            FMA2(acc0[j], scratch[j * 112 + t],       0x3f8000003f800000ull); // +1.0x
            FMA2(acc1[j], scratch[(7 + j) * 112 + t], 0x3f8000003f800000ull);
            float lo, hi;
            asm("mov.b64 {%0, %1}, %2;" : "=f"(lo), "=f"(hi) : "l"(acc0[j]));
            *reinterpret_cast<float2*>(op0 + 2 * j) = make_float2(lo + b, hi + b);
            asm("mov.b64 {%0, %1}, %2;" : "=f"(lo), "=f"(hi) : "l"(acc1[j]));
            *reinterpret_cast<float2*>(op1 + 2 * j) = make_float2(lo + b, hi + b);
        }
    }
}

extern "C" void kernel_launch(void* const* d_in, const int* in_sizes, int n_in,
                              void* d_out, int out_size)
{
    const float* x    = (const float*)d_in[0];
    const float* w    = (const float*)d_in[1];
    const float* bias = (const float*)d_in[2];
    float* out = (float*)d_out;

    // 31648 + 8448 + 12544 = 52640 B
    const int smem_bytes = ROWS * SSTRIDE * 4 + 33 * WROW * 8 + 14 * 112 * 8;

    cudaFuncSetAttribute(dwconv31_f32x2_v6_kernel,
                         cudaFuncAttributeMaxDynamicSharedMemorySize, smem_bytes);
    cudaFuncSetAttribute(dwconv31_f32x2_v6_kernel,
                         cudaFuncAttributePreferredSharedMemoryCarveout, 100);

    dim3 grid(32 * 384);
    dim3 block(NTHREADS);
    dwconv31_f32x2_v6_kernel<<<grid, block, smem_bytes>>>(x, w, bias, out);
}

// round 9
// speedup vs baseline: 1.1977x; 1.0004x over previous
#include <cuda_runtime.h>
#include <cuda_bf16.h>

// Depthwise conv 31x31, pad 15, stride 1, fp32.
// x: [32, 384, 56, 56], w: [384, 1, 31, 31], bias: [384], out: [32, 384, 56, 56]
//
// v6: one block per (n,c) plane, 224 threads = 2 K-halves x (28 row-pairs x 4
// col-groups). Each logical thread computes 2 output rows x 14 cols as 14
// packed f32x2 accumulators over HALF the 31 tap-rows; halves combine via a
// smem reduction. Full 32-lane warps (no half-warp pipe tax) and 21 warps/SM.
//
// Single smem copy of the padded plane. For an output pair and aligned input
// pair pf=(a,b):  acc += pf*dup(w_t) + swap(pf)*(w_{t+1}, w_{t-1}),  t even,
// w_{-1}=w_{31}=0. swap(pf) is 2 MOVs (alu), CSE'd per input pair.
// SSTRIDE=92 (=12 mod 16): pair-bank delta = 12*dy2 + 7*dg (mod 16);
// {4,8,12} never meets {2,5,7,9,11,14} -> conflict-free LDS.64.
// Weight rows stored as 16 ulonglong2: [dup(w_2e), (w_{2e+1},w_{2e-1})],
// with zero guard rows so the r-loop is branch-free.

#define ROWS 86           // 56 + 2*15
#define COLS 86
#define SSTRIDE 92        // floats per row; 92 mod 16 = 12 -> conflict-free
#define PJ (SSTRIDE/2)    // 46 u64 pairs per row
#define WROW 32           // u64 entries per weight row (16 x ulonglong2)
#define NTHREADS 224

typedef unsigned long long u64;

#define FMA2(a, x, w) asm("fma.rn.f32x2 %0, %1, %2, %0;" : "+l"(a) : "l"(x), "l"(w))

__global__ void __launch_bounds__(NTHREADS, 3)
dwconv31_f32x2_v6_kernel(const float* __restrict__ x,
                         const float* __restrict__ w,
                         const float* __restrict__ bias,
                         float* __restrict__ out)
{
    const int plane = blockIdx.x;          // n*384 + c
    const int ch = plane - (plane / 384) * 384;

    extern __shared__ float sm[];
    // [inA: 86*92 f32 = 31648 B][WZ: 33*32 u64 = 8448 B][scratch: 1568 u64 = 12544 B]
    float* inA = sm;
    u64* WZ = (u64*)(sm + ROWS * SSTRIDE);
    u64* scratch = WZ + 33 * WROW;

    const float* xp = x + (long long)plane * (56 * 56);

    // Stage weights. WZ row k holds logical tap-row kk = k-1 (zeros if kk
    // outside 0..30). Entry layout per row: [2e] = dup(w_{2e});
    // [2e+1] = (lo=w_{2e+1} or 0, hi=w_{2e-1} or 0).
    for (int i = threadIdx.x; i < 33 * WROW; i += NTHREADS) {
        int k = i >> 5, s = i & 31, e = s >> 1;
        int kk = k - 1;
        float lo = 0.0f, hi = 0.0f;
        if (kk >= 0 && kk < 31) {
            const float* wr = w + ch * 961 + kk * 31;
            if ((s & 1) == 0) {
                lo = hi = wr[2 * e];
            } else {
                lo = (2 * e + 1 < 31) ? wr[2 * e + 1] : 0.0f;
                hi = (e > 0) ? wr[2 * e - 1] : 0.0f;
            }
        }
        u64 p;
        asm("mov.b64 %0, {%1, %2};" : "=l"(p) : "f"(lo), "f"(hi));
        WZ[i] = p;
    }

    // Stage padded input plane (zero halo).
    for (int i = threadIdx.x; i < ROWS * COLS; i += NTHREADS) {
        int r = i / COLS;
        int c = i - r * COLS;
        int gy = r - 15, gx = c - 15;
        float v = 0.0f;
        if ((unsigned)gy < 56u && (unsigned)gx < 56u)
            v = xp[gy * 56 + gx];
        inA[r * SSTRIDE + c] = v;
    }
    __syncthreads();

    const int half = (threadIdx.x >= 112);
    const int t    = threadIdx.x - half * 112;   // 0..111
    const int y2 = t >> 2;                       // 0..27
    const int y  = y2 * 2;                       // output row base
    const int g  = t & 3;                        // col group
    const int rbase = half * 16;

    u64 acc0[7], acc1[7];
#pragma unroll
    for (int j = 0; j < 7; ++j) { acc0[j] = 0ull; acc1[j] = 0ull; }

#pragma unroll 1
    for (int r = 0; r < 16; ++r) {
        const int rr = rbase + r;
        // Input row y+rr feeds: out row y   with logical weight row rr   (WZ rr+1)
        //                       out row y+1 with logical weight row rr-1 (WZ rr)
        const u64* prow = (const u64*)inA + (y + rr) * PJ + g * 7;
        const ulonglong2* W0 = (const ulonglong2*)(WZ + (rr + 1) * WROW);
        const ulonglong2* W1 = (const ulonglong2*)(WZ + rr * WROW);

#pragma unroll
        for (int e = 0; e < 16; ++e) {
            ulonglong2 wa = W0[e];   // .x = dup even tap, .y = cross pair
            ulonglong2 wb = W1[e];
#pragma unroll
            for (int j = 0; j < 7; ++j) {
                u64 pf = prow[e + j];                 // CSE'd across e+j
                u64 pr;                               // swapped pair (CSE'd)
                asm("{\n\t.reg .b32 lo, hi;\n\t"
                    "mov.b64 {lo, hi}, %1;\n\t"
                    "mov.b64 %0, {hi, lo};\n\t}"
                    : "=l"(pr) : "l"(pf));
                FMA2(acc0[j], pf, wa.x);
                FMA2(acc0[j], pr, wa.y);
                FMA2(acc1[j], pf, wb.x);
                FMA2(acc1[j], pr, wb.y);
            }
        }
    }

    // Split-K reduction: half1 publishes, half0 combines and writes out.
    if (half) {
#pragma unroll
        for (int j = 0; j < 7; ++j) {
            scratch[j * 112 + t]       = acc0[j];
            scratch[(7 + j) * 112 + t] = acc1[j];
        }
    }
    __syncthreads();
    if (!half) {
        const float b = bias[ch];
        float* op0 = out + (long long)plane * (56 * 56) + y * 56 + g * 14;
        float* op1 = op0 + 56;
#pragma unroll
        for (int j = 0; j < 7; ++j) {
            FMA2(acc0[j], scratch[j * 112 + t],       0x3f8000003f800000ull); // +1.0x
            FMA2(acc1[j], scratch[(7 + j) * 112 + t], 0x3f8000003f800000ull);
            float lo, hi;
            asm("mov.b64 {%0, %1}, %2;" : "=f"(lo), "=f"(hi) : "l"(acc0[j]));
            *reinterpret_cast<float2*>(op0 + 2 * j) = make_float2(lo + b, hi + b);
            asm("mov.b64 {%0, %1}, %2;" : "=f"(lo), "=f"(hi) : "l"(acc1[j]));
            *reinterpret_cast<float2*>(op1 + 2 * j) = make_float2(lo + b, hi + b);
        }
    }
}

extern "C" void kernel_launch(void* const* d_in, const int* in_sizes, int n_in,
                              void* d_out, int out_size)
{
    const float* x    = (const float*)d_in[0];
    const float* w    = (const float*)d_in[1];
    const float* bias = (const float*)d_in[2];
    float* out = (float*)d_out;

    // 31648 + 8448 + 12544 = 52640 B
    const int smem_bytes = ROWS * SSTRIDE * 4 + 33 * WROW * 8 + 14 * 112 * 8;

    cudaFuncSetAttribute(dwconv31_f32x2_v6_kernel,
                         cudaFuncAttributeMaxDynamicSharedMemorySize, smem_bytes);
    cudaFuncSetAttribute(dwconv31_f32x2_v6_kernel,
                         cudaFuncAttributePreferredSharedMemoryCarveout, 100);

    dim3 grid(32 * 384);
    dim3 block(NTHREADS);
    dwconv31_f32x2_v6_kernel<<<grid, block, smem_bytes>>>(x, w, bias, out);
}

// round 12
// speedup vs baseline: 3.4437x; 2.8753x over previous
#include <cuda_runtime.h>
#include <cstdint>

// Depthwise conv 31x31, pad 15, stride 1, fp32 — legacy tensor-core path.
// x: [32, 384, 56, 56], w: [384, 1, 31, 31], bias: [384], out same shape.
//
// tcgen05 is unavailable (harness ptxas targets sm_103, not sm_103a), so we
// use baseline PTX mma.sync.m16n8k8 TF32 (sm_80+, runs via fallback HMMA on
// Blackwell). Per CTA = one (n,c) plane. Per tap-row dy:
//     D[y][x] += sum_u InPad[y+dy][u] * W_dy[u][x],  W_dy[u][x] = w[dy][u-x]
// A = padded input rows (the dy shift is just a row offset -> A staged ONCE),
// B = weights, a function of (u-x) only -> 6 distinct 8x8 B fragments per dy,
// read from a 64-entry zero-padded weight line. Band-limited k loop
// (kt-n in [0,5]) keeps FLOP inflation at 1.77x.
// 4 warps: warp w computes D rows y0=16w..y0+15 (rows >=56 masked on store).

typedef unsigned int u32;

#define IPSTRIDE 100     // floats per InPad row; 100 mod 32 = 4 -> A loads conflict-free
#define IPROWS   94      // rows 0..93 (y0+dy+g+8 max = 93), rows >=86 zero
#define NTH      128

static __device__ __forceinline__ u32 tf32r(float v) {
    u32 t;
    asm("cvt.rna.tf32.f32 %0, %1;" : "=r"(t) : "f"(v));
    return t;
}

#define MMA(acc, a, bb0, bb1)                                                  \
    asm("mma.sync.aligned.m16n8k8.row.col.f32.tf32.tf32.f32 "                  \
        "{%0,%1,%2,%3}, {%4,%5,%6,%7}, {%8,%9}, {%0,%1,%2,%3};"                \
        : "+f"((acc)[0]), "+f"((acc)[1]), "+f"((acc)[2]), "+f"((acc)[3])       \
        : "r"((a)[0]), "r"((a)[1]), "r"((a)[2]), "r"((a)[3]),                  \
          "r"(bb0), "r"(bb1))

__global__ void __launch_bounds__(NTH, 4)
dwconv31_tf32_hmma_kernel(const float* __restrict__ x,
                          const float* __restrict__ w,
                          const float* __restrict__ bias,
                          float* __restrict__ out)
{
    extern __shared__ u32 sm[];
    u32* ip   = sm;                    // InPad: 94 x 100 tf32
    u32* wall = sm + IPROWS * IPSTRIDE; // 31 x 64 padded weight lines

    const int plane = blockIdx.x;          // n*384 + c
    const int c = plane - (plane / 384) * 384;
    const int tid = threadIdx.x;

    // Zero InPad (halo, pad rows, pad cols), stage padded weight lines.
#pragma unroll 1
    for (int i = tid; i < IPROWS * IPSTRIDE; i += NTH) ip[i] = 0u;
#pragma unroll 1
    for (int i = tid; i < 31 * 64; i += NTH) {
        int dy = i >> 6, p = i & 63, t = p - 8;
        float v = (t >= 0 && t < 31) ? w[c * 961 + dy * 31 + t] : 0.0f;
        wall[i] = tf32r(v);
    }
    __syncthreads();
    // Fill interior: InPad[gy+15][gx+15] = x[gy][gx], tf32-rounded.
    const float* xp = x + (long long)plane * 3136;
#pragma unroll 1
    for (int i = tid; i < 3136; i += NTH) {
        int gy = i / 56, gx = i - gy * 56;
        ip[(gy + 15) * IPSTRIDE + gx + 15] = tf32r(xp[i]);
    }
    __syncthreads();

    const int lane = tid & 31, warp = tid >> 5;
    const int g = lane >> 2, tg = lane & 3;   // groupID, thread-in-group
    const int y0 = warp * 16;

    float acc[7][4];
#pragma unroll
    for (int n = 0; n < 7; ++n)
#pragma unroll
        for (int q = 0; q < 4; ++q) acc[n][q] = 0.0f;

#pragma unroll 1
    for (int dy = 0; dy < 31; ++dy) {
        // B fragments: b(j) covers W[u][x] tile with u-tile = n+j, x-tile = n.
        // Element = wline[8*(kt-n) + (tg or tg+4) - g], independent of n.
        const u32* wl = wall + dy * 64 + 8;   // wl[d] = w[dy][d] (zero-padded)
        u32 b0[6], b1[6];
#pragma unroll
        for (int j = 0; j < 6; ++j) {
            b0[j] = wl[8 * j + tg - g];
            b1[j] = wl[8 * j + 4 + tg - g];
        }
        // A fragments: 12 k-tiles of InPad rows y0+dy+{g, g+8}.
        const u32* r0 = ip + (y0 + dy + g) * IPSTRIDE;
        const u32* r1 = r0 + 8 * IPSTRIDE;
        u32 a[12][4];
#pragma unroll
        for (int k = 0; k < 12; ++k) {
            a[k][0] = r0[8 * k + tg];
            a[k][1] = r1[8 * k + tg];
            a[k][2] = r0[8 * k + tg + 4];
            a[k][3] = r1[8 * k + tg + 4];
        }
        // Band-limited GEMM: D n-tile n uses k-tiles n..n+5.
#pragma unroll
        for (int n = 0; n < 7; ++n)
#pragma unroll
            for (int j = 0; j < 6; ++j)
                MMA(acc[n], a[n + j], b0[j], b1[j]);
    }

    // Epilogue: c0=D[g][2tg], c1=D[g][2tg+1], c2/c3 = rows g+8.
    const float bv = bias[c];
    float* op = out + (long long)plane * 3136;
    const int ylo = y0 + g, yhi = ylo + 8;   // ylo always < 56; yhi may be >=56
#pragma unroll
    for (int n = 0; n < 7; ++n) {
        const int xcol = 8 * n + 2 * tg;
        *reinterpret_cast<float2*>(op + ylo * 56 + xcol) =
            make_float2(acc[n][0] + bv, acc[n][1] + bv);
        if (yhi < 56)
            *reinterpret_cast<float2*>(op + yhi * 56 + xcol) =
                make_float2(acc[n][2] + bv, acc[n][3] + bv);
    }
}

extern "C" void kernel_launch(void* const* d_in, const int* in_sizes, int n_in,
                              void* d_out, int out_size)
{
    const float* x    = (const float*)d_in[0];
    const float* w    = (const float*)d_in[1];
    const float* bias = (const float*)d_in[2];
    float* out = (float*)d_out;

    // 94*100*4 + 31*64*4 = 37600 + 7936 = 45536 B
    const int smem_bytes = (IPROWS * IPSTRIDE + 31 * 64) * 4;

    cudaFuncSetAttribute(dwconv31_tf32_hmma_kernel,
                         cudaFuncAttributeMaxDynamicSharedMemorySize, smem_bytes);
    cudaFuncSetAttribute(dwconv31_tf32_hmma_kernel,
                         cudaFuncAttributePreferredSharedMemoryCarveout, 100);

    dim3 grid(32 * 384);
    dim3 block(NTH);
    dwconv31_tf32_hmma_kernel<<<grid, block, smem_bytes>>>(x, w, bias, out);
}

// round 13
// speedup vs baseline: 3.7594x; 1.0917x over previous
#include <cuda_runtime.h>
#include <cstdint>

// Depthwise conv 31x31, pad 15, stride 1, fp32 — legacy tensor-core path.
// x: [32, 384, 56, 56], w: [384, 1, 31, 31], bias: [384], out same shape.
//
// mma.sync.m16n8k8 TF32 (sm_80+ PTX; runs on Blackwell tensor pipe via
// fallback HMMA — tcgen05 is blocked because the harness targets sm_103).
// Per CTA = one (n,c) plane. Per tap-row dy:
//     D[y][x] += sum_u InPad[y+dy][u] * W_dy[u][x],  W_dy[u][x] = w[dy][u-x]
// A = padded input rows (dy shift = row offset; staged once), B = weights,
// function of (u-x) only -> read from a 64-entry zero-padded weight line.
//
// R12: band tightened to j in [0,4] — the j=5 B-fragment indices 8*5+{tg,tg+4}-g
// lie in [33,47], entirely outside weight support [0,30], so those MMAs were
// multiplying by zero. 42 -> 35 MMAs/dy (-16.7% tensor work). A k-tiles 12 -> 11.
// Occupancy 4 -> 5 CTAs/SM (5 x 45536 B = 227.7 KB fits the 228 KB carveout).

typedef unsigned int u32;

#define IPSTRIDE 100     // floats per InPad row; 100 mod 32 = 4 -> A loads conflict-free
#define IPROWS   94      // rows 0..93 (y0+dy+g+8 max = 93), rows >=86 zero
#define NTH      128

static __device__ __forceinline__ u32 tf32r(float v) {
    u32 t;
    asm("cvt.rna.tf32.f32 %0, %1;" : "=r"(t) : "f"(v));
    return t;
}

#define MMA(acc, a, bb0, bb1)                                                  \
    asm("mma.sync.aligned.m16n8k8.row.col.f32.tf32.tf32.f32 "                  \
        "{%0,%1,%2,%3}, {%4,%5,%6,%7}, {%8,%9}, {%0,%1,%2,%3};"                \
        : "+f"((acc)[0]), "+f"((acc)[1]), "+f"((acc)[2]), "+f"((acc)[3])       \
        : "r"((a)[0]), "r"((a)[1]), "r"((a)[2]), "r"((a)[3]),                  \
          "r"(bb0), "r"(bb1))

__global__ void __launch_bounds__(NTH, 5)
dwconv31_tf32_hmma2_kernel(const float* __restrict__ x,
                           const float* __restrict__ w,
                           const float* __restrict__ bias,
                           float* __restrict__ out)
{
    extern __shared__ u32 sm[];
    u32* ip   = sm;                     // InPad: 94 x 100 tf32
    u32* wall = sm + IPROWS * IPSTRIDE; // 31 x 64 padded weight lines

    const int plane = blockIdx.x;          // n*384 + c
    const int c = plane - (plane / 384) * 384;
    const int tid = threadIdx.x;

    // Zero InPad (halo rows/cols), stage zero-padded weight lines.
#pragma unroll 1
    for (int i = tid; i < IPROWS * IPSTRIDE; i += NTH) ip[i] = 0u;
#pragma unroll 1
    for (int i = tid; i < 31 * 64; i += NTH) {
        int dy = i >> 6, p = i & 63, t = p - 8;
        float v = (t >= 0 && t < 31) ? w[c * 961 + dy * 31 + t] : 0.0f;
        wall[i] = tf32r(v);
    }
    __syncthreads();
    // Fill interior: InPad[gy+15][gx+15] = x[gy][gx], tf32-rounded.
    const float* xp = x + (long long)plane * 3136;
#pragma unroll 1
    for (int i = tid; i < 3136; i += NTH) {
        int gy = i / 56, gx = i - gy * 56;
        ip[(gy + 15) * IPSTRIDE + gx + 15] = tf32r(xp[i]);
    }
    __syncthreads();

    const int lane = tid & 31, warp = tid >> 5;
    const int g = lane >> 2, tg = lane & 3;   // groupID, thread-in-group
    const int y0 = warp * 16;

    float acc[7][4];
#pragma unroll
    for (int n = 0; n < 7; ++n)
#pragma unroll
        for (int q = 0; q < 4; ++q) acc[n][q] = 0.0f;

#pragma unroll 1
    for (int dy = 0; dy < 31; ++dy) {
        // B fragments: element = wl[8j + (tg|tg+4) - g], j = k-tile - n-tile.
        const u32* wl = wall + dy * 64 + 8;   // wl[d] = w[dy][d] (zero-padded)
        u32 b0[5], b1[5];
#pragma unroll
        for (int j = 0; j < 5; ++j) {
            b0[j] = wl[8 * j + tg - g];
            b1[j] = wl[8 * j + 4 + tg - g];
        }
        // A fragments: 11 k-tiles of InPad rows y0+dy+{g, g+8}.
        const u32* r0 = ip + (y0 + dy + g) * IPSTRIDE;
        const u32* r1 = r0 + 8 * IPSTRIDE;
        u32 a[11][4];
#pragma unroll
        for (int k = 0; k < 11; ++k) {
            a[k][0] = r0[8 * k + tg];
            a[k][1] = r1[8 * k + tg];
            a[k][2] = r0[8 * k + tg + 4];
            a[k][3] = r1[8 * k + tg + 4];
        }
        // Band-limited GEMM: D n-tile n uses k-tiles n..n+4.
#pragma unroll
        for (int n = 0; n < 7; ++n)
#pragma unroll
            for (int j = 0; j < 5; ++j)
                MMA(acc[n], a[n + j], b0[j], b1[j]);
    }

    // Epilogue: c0=D[g][2tg], c1=D[g][2tg+1], c2/c3 = rows g+8.
    const float bv = bias[c];
    float* op = out + (long long)plane * 3136;
    const int ylo = y0 + g, yhi = ylo + 8;   // ylo < 56 always; yhi may be >= 56
#pragma unroll
    for (int n = 0; n < 7; ++n) {
        const int xcol = 8 * n + 2 * tg;
        *reinterpret_cast<float2*>(op + ylo * 56 + xcol) =
            make_float2(acc[n][0] + bv, acc[n][1] + bv);
        if (yhi < 56)
            *reinterpret_cast<float2*>(op + yhi * 56 + xcol) =
                make_float2(acc[n][2] + bv, acc[n][3] + bv);
    }
}

extern "C" void kernel_launch(void* const* d_in, const int* in_sizes, int n_in,
                              void* d_out, int out_size)
{
    const float* x    = (const float*)d_in[0];
    const float* w    = (const float*)d_in[1];
    const float* bias = (const float*)d_in[2];
    float* out = (float*)d_out;

    // 94*100*4 + 31*64*4 = 45536 B; 5 CTAs/SM = 227.7 KB
    const int smem_bytes = (IPROWS * IPSTRIDE + 31 * 64) * 4;

    cudaFuncSetAttribute(dwconv31_tf32_hmma2_kernel,
                         cudaFuncAttributeMaxDynamicSharedMemorySize, smem_bytes);
    cudaFuncSetAttribute(dwconv31_tf32_hmma2_kernel,
                         cudaFuncAttributePreferredSharedMemoryCarveout, 100);

    dim3 grid(32 * 384);
    dim3 block(NTH);
    dwconv31_tf32_hmma2_kernel<<<grid, block, smem_bytes>>>(x, w, bias, out);
}